// round 15
// baseline (speedup 1.0000x reference)
#include <cuda_runtime.h>
#include <stdint.h>

#define NB 4
#define NN 512
#define DD 128
#define H1C 64
#define H2C 32
#define NT 8                       // 512/64 tiles
#define NPAIRS (NT * (NT + 1) / 2) // 36
#define THREADS 512

// ---- dynamic shared memory layout (bytes) ----
#define OFF_VIH  0                 // 64*68*4 = 17408
#define OFF_VJH  17408             // 17408
#define OFF_W1F  34816             // 8 ks x 32 lane x 16 u32 = 16384
#define OFF_W2F  51200             // 4 ks x 32 lane x 8 u32 = 4096
#define OFF_B1S  55296             // 64 f
#define OFF_B2S  55552             // 32 f
#define SMEM_TOTAL 55680

static __device__ __forceinline__ uint32_t packh2(float lo, float hi) {
    uint32_t u;
    asm("cvt.rn.f16x2.f32 %0, %1, %2;" : "=r"(u) : "f"(hi), "f"(lo));
    return u;
}
static __device__ __forceinline__ uint32_t habs2_sub(uint32_t a, uint32_t b) {
    uint32_t d;
    asm("sub.f16x2 %0, %1, %2;" : "=r"(d) : "r"(a), "r"(b));
    return d & 0x7FFF7FFFu;
}
static __device__ __forceinline__ void mma_f16(float* c,
        uint32_t a0, uint32_t a1, uint32_t a2, uint32_t a3,
        uint32_t b0, uint32_t b1) {
    asm volatile(
        "mma.sync.aligned.m16n8k16.row.col.f32.f16.f16.f32 "
        "{%0,%1,%2,%3}, {%4,%5,%6,%7}, {%8,%9}, {%0,%1,%2,%3};"
        : "+f"(c[0]), "+f"(c[1]), "+f"(c[2]), "+f"(c[3])
        : "r"(a0), "r"(a1), "r"(a2), "r"(a3), "r"(b0), "r"(b1));
}
static __device__ __forceinline__ float leaky(float x) { return fmaxf(x, 0.1f * x); }

// ---------------------------------------------------------------------------
// Symmetric fp16-HMMA logits kernel: 16 warps (4/SMSP), 2-i-row blocking,
// weights in SMEM fragment tables, <=128 regs -> high warp concurrency to
// hide MMA/LDS latency.  Shuffle-free dot-MMA layer 3.
// CTA = (batch, tile-pair ti<=tj, 64x64); warp w owns i-rows w*4..w*4+3.
// ---------------------------------------------------------------------------
__global__ __launch_bounds__(THREADS, 1)
void adj_hmma_kernel(const float* __restrict__ v,
                     const float* __restrict__ W1, const float* __restrict__ b1,
                     const float* __restrict__ W2, const float* __restrict__ b2,
                     const float* __restrict__ W3, const float* __restrict__ b3,
                     float* __restrict__ out)
{
    extern __shared__ char sm[];
    uint32_t* VIH = (uint32_t*)(sm + OFF_VIH);
    uint32_t* VJH = (uint32_t*)(sm + OFF_VJH);
    uint32_t* W1F = (uint32_t*)(sm + OFF_W1F);
    uint32_t* W2F = (uint32_t*)(sm + OFF_W2F);
    float*    B1S = (float*)(sm + OFF_B1S);
    float*    B2S = (float*)(sm + OFF_B2S);

    const int tid  = threadIdx.x;
    const int wid  = tid >> 5;
    const int lane = tid & 31;
    const int g    = lane >> 2;   // groupID (row within fragment)
    const int t    = lane & 3;    // threadID_in_group
    const int b    = blockIdx.y;

    // decode (ti, tj), ti <= tj
    int rem = blockIdx.x;
    int ti = 0;
    while (rem >= NT - ti) { rem -= NT - ti; ti++; }
    const int tj = ti + rem;

    // ---- stage v tiles -> half2 SMEM (rows padded to 68 u32) ----
    const float* vb = v + (size_t)b * NN * DD;
    for (int e = tid; e < 64 * 32; e += THREADS) {
        int r = e >> 5, c = e & 31;
        float4 xi = ((const float4*)(vb + (size_t)(ti * 64 + r) * DD))[c];
        float4 xj = ((const float4*)(vb + (size_t)(tj * 64 + r) * DD))[c];
        VIH[r * 68 + 2 * c]     = packh2(xi.x, xi.y);
        VIH[r * 68 + 2 * c + 1] = packh2(xi.z, xi.w);
        VJH[r * 68 + 2 * c]     = packh2(xj.x, xj.y);
        VJH[r * 68 + 2 * c + 1] = packh2(xj.z, xj.w);
    }
    // ---- W1 half2 fragments: [ks(8)][lane(32)][n(8)x{b0,b1}] ----
    for (int idx = tid; idx < 8 * 32 * 16; idx += THREADS) {
        int ks = idx >> 9, ln = (idx >> 4) & 31, rm = idx & 15;
        int n = rm >> 1, e = rm & 1;
        int o  = (ln >> 2) + 8 * n;
        int kb = 16 * ks + 2 * (ln & 3) + 8 * e;
        W1F[idx] = packh2(W1[o * DD + kb], W1[o * DD + kb + 1]);
    }
    // ---- W2 half2 fragments: [ks(4)][lane(32)][n(4)x{b0,b1}] ----
    for (int idx = tid; idx < 4 * 32 * 8; idx += THREADS) {
        int ks = idx >> 8, ln = (idx >> 3) & 31, rm = idx & 7;
        int n = rm >> 1, e = rm & 1;
        int o  = (ln >> 2) + 8 * n;
        int kb = 16 * ks + 2 * (ln & 3) + 8 * e;
        W2F[idx] = packh2(W2[o * H1C + kb], W2[o * H1C + kb + 1]);
    }
    if (tid < H1C) B1S[tid] = b1[tid];
    if (tid < H2C) B2S[tid] = b2[tid];
    const float bias3 = b3[0];

    // w3 B-fragments, replicated across columns (independent of g): 4 regs
    uint32_t w3f[4];
    #pragma unroll
    for (int ks = 0; ks < 2; ++ks)
        #pragma unroll
        for (int e = 0; e < 2; ++e) {
            int k = 16 * ks + 2 * t + 8 * e;
            w3f[2 * ks + e] = packh2(W3[k], W3[k + 1]);
        }
    __syncthreads();

    float* ob = out + (size_t)b * NN * NN;

    for (int jm = 0; jm < 4; ++jm) {
        const uint32_t* vj0p = VJH + (jm * 16 + g) * 68;
        const uint32_t* vj1p = VJH + (jm * 16 + 8 + g) * 68;

        #pragma unroll 1
        for (int rp = 0; rp < 2; ++rp) {
            const int il0 = wid * 4 + rp * 2;
            const int ig0 = ti * 64 + il0;

            // ---- GEMM1 (2 rows): h1 = |vi - vj| @ W1^T,  K = 128 ----
            float c1[2][8][4];
            #pragma unroll
            for (int n = 0; n < 8; ++n) {
                float bb0 = B1S[8 * n + 2 * t];
                float bb1 = B1S[8 * n + 2 * t + 1];
                #pragma unroll
                for (int r = 0; r < 2; ++r) {
                    c1[r][n][0] = bb0;  c1[r][n][1] = bb1;
                    c1[r][n][2] = bb0;  c1[r][n][3] = bb1;
                }
            }
            #pragma unroll
            for (int ks = 0; ks < 8; ++ks) {
                uint32_t j0l = vj0p[8 * ks + t];
                uint32_t j1l = vj1p[8 * ks + t];
                uint32_t j0h = vj0p[8 * ks + t + 4];
                uint32_t j1h = vj1p[8 * ks + t + 4];
                uint32_t vl0 = VIH[il0 * 68 + 8 * ks + t];
                uint32_t vh0 = VIH[il0 * 68 + 8 * ks + t + 4];
                uint32_t vl1 = VIH[(il0 + 1) * 68 + 8 * ks + t];
                uint32_t vh1 = VIH[(il0 + 1) * 68 + 8 * ks + t + 4];
                uint32_t a00 = habs2_sub(vl0, j0l);
                uint32_t a10 = habs2_sub(vl0, j1l);
                uint32_t a20 = habs2_sub(vh0, j0h);
                uint32_t a30 = habs2_sub(vh0, j1h);
                uint32_t a01 = habs2_sub(vl1, j0l);
                uint32_t a11 = habs2_sub(vl1, j1l);
                uint32_t a21 = habs2_sub(vh1, j0h);
                uint32_t a31 = habs2_sub(vh1, j1h);
                const uint32_t* wq = W1F + ks * 512 + lane * 16;
                #pragma unroll
                for (int n = 0; n < 8; ++n) {
                    uint32_t w0 = wq[2 * n], w1r = wq[2 * n + 1];
                    mma_f16(c1[0][n], a00, a10, a20, a30, w0, w1r);
                    mma_f16(c1[1][n], a01, a11, a21, a31, w0, w1r);
                }
            }

            // ---- per row: GEMM2 then dot-MMA (no shuffles) ----
            #pragma unroll
            for (int r = 0; r < 2; ++r) {
                float c2[4][4];
                #pragma unroll
                for (int n = 0; n < 4; ++n) {
                    c2[n][0] = B2S[8 * n + 2 * t];
                    c2[n][1] = B2S[8 * n + 2 * t + 1];
                    c2[n][2] = c2[n][0];
                    c2[n][3] = c2[n][1];
                }
                #pragma unroll
                for (int ks = 0; ks < 4; ++ks) {
                    uint32_t a0 = packh2(leaky(c1[r][2 * ks][0]),     leaky(c1[r][2 * ks][1]));
                    uint32_t a1 = packh2(leaky(c1[r][2 * ks][2]),     leaky(c1[r][2 * ks][3]));
                    uint32_t a2 = packh2(leaky(c1[r][2 * ks + 1][0]), leaky(c1[r][2 * ks + 1][1]));
                    uint32_t a3 = packh2(leaky(c1[r][2 * ks + 1][2]), leaky(c1[r][2 * ks + 1][3]));
                    const uint32_t* wq = W2F + ks * 256 + lane * 8;
                    #pragma unroll
                    for (int n = 0; n < 4; ++n)
                        mma_f16(c2[n], a0, a1, a2, a3, wq[2 * n], wq[2 * n + 1]);
                }

                // layer-3 dot as MMA: c[0]=row g, c[2]=row g+8 on all threads
                float cd[4] = {bias3, bias3, bias3, bias3};
                #pragma unroll
                for (int ks = 0; ks < 2; ++ks) {
                    uint32_t a0 = packh2(leaky(c2[2 * ks][0]),     leaky(c2[2 * ks][1]));
                    uint32_t a1 = packh2(leaky(c2[2 * ks][2]),     leaky(c2[2 * ks][3]));
                    uint32_t a2 = packh2(leaky(c2[2 * ks + 1][0]), leaky(c2[2 * ks + 1][1]));
                    uint32_t a3 = packh2(leaky(c2[2 * ks + 1][2]), leaky(c2[2 * ks + 1][3]));
                    mma_f16(cd, a0, a1, a2, a3, w3f[2 * ks], w3f[2 * ks + 1]);
                }

                if (t == 0) {
                    const int ig = ig0 + r;
                    const int jg = tj * 64 + jm * 16 + g;
                    ob[(size_t)ig * NN + jg]     = cd[0];
                    ob[(size_t)ig * NN + jg + 8] = cd[2];
                    if (ti != tj) {   // mirror (logits exactly symmetric)
                        ob[(size_t)jg * NN + ig]       = cd[0];
                        ob[(size_t)(jg + 8) * NN + ig] = cd[2];
                    }
                }
            }
        }
    }
}

// ---------------------------------------------------------------------------
// Row softmax, warp-per-row: 16 rows per 512-thread block, 128 blocks.
// ---------------------------------------------------------------------------
__global__ __launch_bounds__(512)
void adj_softmax_kernel(float* __restrict__ out)
{
    const int row  = blockIdx.x * 16 + (threadIdx.x >> 5);
    const int lane = threadIdx.x & 31;
    float4* __restrict__ p = (float4*)(out + (size_t)row * NN);

    float4 x0 = p[lane];
    float4 x1 = p[lane + 32];
    float4 x2 = p[lane + 64];
    float4 x3 = p[lane + 96];

    float m = fmaxf(fmaxf(fmaxf(x0.x, x0.y), fmaxf(x0.z, x0.w)),
                    fmaxf(fmaxf(x1.x, x1.y), fmaxf(x1.z, x1.w)));
    m = fmaxf(m, fmaxf(fmaxf(fmaxf(x2.x, x2.y), fmaxf(x2.z, x2.w)),
                       fmaxf(fmaxf(x3.x, x3.y), fmaxf(x3.z, x3.w))));
    #pragma unroll
    for (int o = 16; o; o >>= 1) m = fmaxf(m, __shfl_xor_sync(0xFFFFFFFFu, m, o));

    x0.x = __expf(x0.x - m); x0.y = __expf(x0.y - m);
    x0.z = __expf(x0.z - m); x0.w = __expf(x0.w - m);
    x1.x = __expf(x1.x - m); x1.y = __expf(x1.y - m);
    x1.z = __expf(x1.z - m); x1.w = __expf(x1.w - m);
    x2.x = __expf(x2.x - m); x2.y = __expf(x2.y - m);
    x2.z = __expf(x2.z - m); x2.w = __expf(x2.w - m);
    x3.x = __expf(x3.x - m); x3.y = __expf(x3.y - m);
    x3.z = __expf(x3.z - m); x3.w = __expf(x3.w - m);

    float s = ((x0.x + x0.y) + (x0.z + x0.w)) + ((x1.x + x1.y) + (x1.z + x1.w))
            + ((x2.x + x2.y) + (x2.z + x2.w)) + ((x3.x + x3.y) + (x3.z + x3.w));
    #pragma unroll
    for (int o = 16; o; o >>= 1) s += __shfl_xor_sync(0xFFFFFFFFu, s, o);

    float inv = __fdividef(1.0f, s);
    x0.x *= inv; x0.y *= inv; x0.z *= inv; x0.w *= inv;
    x1.x *= inv; x1.y *= inv; x1.z *= inv; x1.w *= inv;
    x2.x *= inv; x2.y *= inv; x2.z *= inv; x2.w *= inv;
    x3.x *= inv; x3.y *= inv; x3.z *= inv; x3.w *= inv;

    p[lane]      = x0;
    p[lane + 32] = x1;
    p[lane + 64] = x2;
    p[lane + 96] = x3;
}

extern "C" void kernel_launch(void* const* d_in, const int* in_sizes, int n_in,
                              void* d_out, int out_size)
{
    const float* v  = (const float*)d_in[0];
    const float* W1 = (const float*)d_in[1];
    const float* b1 = (const float*)d_in[2];
    const float* W2 = (const float*)d_in[3];
    const float* b2 = (const float*)d_in[4];
    const float* W3 = (const float*)d_in[5];
    const float* b3 = (const float*)d_in[6];
    float* out = (float*)d_out;

    cudaFuncSetAttribute(adj_hmma_kernel,
                         cudaFuncAttributeMaxDynamicSharedMemorySize, SMEM_TOTAL);

    dim3 grid(NPAIRS, NB);   // (36, 4) — one wave of 144 CTAs
    adj_hmma_kernel<<<grid, THREADS, SMEM_TOTAL>>>(v, W1, b1, W2, b2, W3, b3, out);
    adj_softmax_kernel<<<NB * NN / 16, 512>>>(out);
}

// round 16
// speedup vs baseline: 1.2574x; 1.2574x over previous
#include <cuda_runtime.h>
#include <stdint.h>

#define NB 4
#define NN 512
#define DD 128
#define H1C 64
#define H2C 32
#define NT 8                       // 512/64 tiles
#define NPAIRS (NT * (NT + 1) / 2) // 36
#define THREADS 256

// ---- dynamic shared memory layout (bytes) ----
#define OFF_VIH  0                 // 64*68*4 = 17408
#define OFF_VJH  17408             // 17408
#define OFF_W1F  34816             // 8 ks x 32 lane x 16 u32 = 16384
#define OFF_W2F  51200             // 4 ks x 32 lane x 8 u32 = 4096
#define OFF_B1S  55296             // 64 f
#define OFF_B2S  55552             // 32 f
#define SMEM_TOTAL 55680

static __device__ __forceinline__ uint32_t packh2(float lo, float hi) {
    uint32_t u;
    asm("cvt.rn.f16x2.f32 %0, %1, %2;" : "=r"(u) : "f"(hi), "f"(lo));
    return u;
}
static __device__ __forceinline__ uint32_t habs2_sub(uint32_t a, uint32_t b) {
    uint32_t d;
    asm("sub.f16x2 %0, %1, %2;" : "=r"(d) : "r"(a), "r"(b));
    return d & 0x7FFF7FFFu;
}
static __device__ __forceinline__ void mma_f16(float* c,
        uint32_t a0, uint32_t a1, uint32_t a2, uint32_t a3,
        uint32_t b0, uint32_t b1) {
    asm volatile(
        "mma.sync.aligned.m16n8k16.row.col.f32.f16.f16.f32 "
        "{%0,%1,%2,%3}, {%4,%5,%6,%7}, {%8,%9}, {%0,%1,%2,%3};"
        : "+f"(c[0]), "+f"(c[1]), "+f"(c[2]), "+f"(c[3])
        : "r"(a0), "r"(a1), "r"(a2), "r"(a3), "r"(b0), "r"(b1));
}
static __device__ __forceinline__ float leaky(float x) { return fmaxf(x, 0.1f * x); }

// ---------------------------------------------------------------------------
// Symmetric fp16-HMMA logits kernel: 4-i-row register blocking with weights
// in SMEM (amortized 4x), and a FULLY INTERLEAVED 4-row GEMM2 + dot-MMA
// tail (16 concurrent MMA chains in GEMM2, 4 in the dot; no shuffles).
// CTA = (batch, tile-pair ti<=tj, 64x64); 8 warps; warp w owns i-rows
// w*8..w*8+7 as two 4-row units.  1 CTA/SM, one wave of 144.
// ---------------------------------------------------------------------------
__global__ __launch_bounds__(THREADS, 1)
void adj_hmma_kernel(const float* __restrict__ v,
                     const float* __restrict__ W1, const float* __restrict__ b1,
                     const float* __restrict__ W2, const float* __restrict__ b2,
                     const float* __restrict__ W3, const float* __restrict__ b3,
                     float* __restrict__ out)
{
    extern __shared__ char sm[];
    uint32_t* VIH = (uint32_t*)(sm + OFF_VIH);
    uint32_t* VJH = (uint32_t*)(sm + OFF_VJH);
    uint32_t* W1F = (uint32_t*)(sm + OFF_W1F);
    uint32_t* W2F = (uint32_t*)(sm + OFF_W2F);
    float*    B1S = (float*)(sm + OFF_B1S);
    float*    B2S = (float*)(sm + OFF_B2S);

    const int tid  = threadIdx.x;
    const int wid  = tid >> 5;
    const int lane = tid & 31;
    const int g    = lane >> 2;   // groupID (row within fragment)
    const int t    = lane & 3;    // threadID_in_group
    const int b    = blockIdx.y;

    // decode (ti, tj), ti <= tj
    int rem = blockIdx.x;
    int ti = 0;
    while (rem >= NT - ti) { rem -= NT - ti; ti++; }
    const int tj = ti + rem;

    // ---- stage v tiles -> half2 SMEM (rows padded to 68 u32) ----
    const float* vb = v + (size_t)b * NN * DD;
    for (int e = tid; e < 64 * 32; e += THREADS) {
        int r = e >> 5, c = e & 31;
        float4 xi = ((const float4*)(vb + (size_t)(ti * 64 + r) * DD))[c];
        float4 xj = ((const float4*)(vb + (size_t)(tj * 64 + r) * DD))[c];
        VIH[r * 68 + 2 * c]     = packh2(xi.x, xi.y);
        VIH[r * 68 + 2 * c + 1] = packh2(xi.z, xi.w);
        VJH[r * 68 + 2 * c]     = packh2(xj.x, xj.y);
        VJH[r * 68 + 2 * c + 1] = packh2(xj.z, xj.w);
    }
    // ---- W1 half2 fragments: [ks(8)][lane(32)][n(8)x{b0,b1}] ----
    for (int idx = tid; idx < 8 * 32 * 16; idx += THREADS) {
        int ks = idx >> 9, ln = (idx >> 4) & 31, rm = idx & 15;
        int n = rm >> 1, e = rm & 1;
        int o  = (ln >> 2) + 8 * n;
        int kb = 16 * ks + 2 * (ln & 3) + 8 * e;
        W1F[idx] = packh2(W1[o * DD + kb], W1[o * DD + kb + 1]);
    }
    // ---- W2 half2 fragments: [ks(4)][lane(32)][n(4)x{b0,b1}] ----
    for (int idx = tid; idx < 4 * 32 * 8; idx += THREADS) {
        int ks = idx >> 8, ln = (idx >> 3) & 31, rm = idx & 7;
        int n = rm >> 1, e = rm & 1;
        int o  = (ln >> 2) + 8 * n;
        int kb = 16 * ks + 2 * (ln & 3) + 8 * e;
        W2F[idx] = packh2(W2[o * H1C + kb], W2[o * H1C + kb + 1]);
    }
    if (tid < H1C) B1S[tid] = b1[tid];
    if (tid < H2C) B2S[tid] = b2[tid];
    const float bias3 = b3[0];

    // w3 B-fragments, replicated across columns (independent of g): 4 regs
    uint32_t w3f[4];
    #pragma unroll
    for (int ks = 0; ks < 2; ++ks)
        #pragma unroll
        for (int e = 0; e < 2; ++e) {
            int k = 16 * ks + 2 * t + 8 * e;
            w3f[2 * ks + e] = packh2(W3[k], W3[k + 1]);
        }
    __syncthreads();

    float* ob = out + (size_t)b * NN * NN;

    for (int ip = 0; ip < 2; ++ip) {
        const int il0 = wid * 8 + ip * 4;     // first of 4 i-rows
        const int ig0 = ti * 64 + il0;

        for (int jm = 0; jm < 4; ++jm) {
            const uint32_t* vj0 = VJH + (jm * 16 + g) * 68;
            const uint32_t* vj1 = VJH + (jm * 16 + 8 + g) * 68;

            // ---- GEMM1 (4 i-rows): h1 = |vi - vj| @ W1^T,  K = 128 ----
            float c1[4][8][4];
            #pragma unroll
            for (int n = 0; n < 8; ++n) {
                float bb0 = B1S[8 * n + 2 * t];
                float bb1 = B1S[8 * n + 2 * t + 1];
                #pragma unroll
                for (int r = 0; r < 4; ++r) {
                    c1[r][n][0] = bb0;  c1[r][n][1] = bb1;
                    c1[r][n][2] = bb0;  c1[r][n][3] = bb1;
                }
            }
            #pragma unroll
            for (int ks = 0; ks < 8; ++ks) {
                uint32_t j0l = vj0[8 * ks + t];
                uint32_t j1l = vj1[8 * ks + t];
                uint32_t j0h = vj0[8 * ks + t + 4];
                uint32_t j1h = vj1[8 * ks + t + 4];
                uint32_t af[4][4];
                #pragma unroll
                for (int r = 0; r < 4; ++r) {
                    uint32_t vlo = VIH[(il0 + r) * 68 + 8 * ks + t];
                    uint32_t vhi = VIH[(il0 + r) * 68 + 8 * ks + t + 4];
                    af[r][0] = habs2_sub(vlo, j0l);
                    af[r][1] = habs2_sub(vlo, j1l);
                    af[r][2] = habs2_sub(vhi, j0h);
                    af[r][3] = habs2_sub(vhi, j1h);
                }
                const uint32_t* wq = W1F + ks * 512 + lane * 16;
                #pragma unroll
                for (int n = 0; n < 8; ++n) {
                    uint32_t w0 = wq[2 * n], w1r = wq[2 * n + 1];
                    #pragma unroll
                    for (int r = 0; r < 4; ++r)
                        mma_f16(c1[r][n], af[r][0], af[r][1], af[r][2], af[r][3], w0, w1r);
                }
            }

            // ---- GEMM2, all 4 rows interleaved (16 concurrent chains) ----
            float c2[4][4][4];
            #pragma unroll
            for (int n = 0; n < 4; ++n) {
                float bb0 = B2S[8 * n + 2 * t];
                float bb1 = B2S[8 * n + 2 * t + 1];
                #pragma unroll
                for (int r = 0; r < 4; ++r) {
                    c2[r][n][0] = bb0;  c2[r][n][1] = bb1;
                    c2[r][n][2] = bb0;  c2[r][n][3] = bb1;
                }
            }
            #pragma unroll
            for (int ks = 0; ks < 4; ++ks) {
                uint32_t af[4][4];
                #pragma unroll
                for (int r = 0; r < 4; ++r) {
                    af[r][0] = packh2(leaky(c1[r][2 * ks][0]),     leaky(c1[r][2 * ks][1]));
                    af[r][1] = packh2(leaky(c1[r][2 * ks][2]),     leaky(c1[r][2 * ks][3]));
                    af[r][2] = packh2(leaky(c1[r][2 * ks + 1][0]), leaky(c1[r][2 * ks + 1][1]));
                    af[r][3] = packh2(leaky(c1[r][2 * ks + 1][2]), leaky(c1[r][2 * ks + 1][3]));
                }
                const uint32_t* wq = W2F + ks * 256 + lane * 8;
                #pragma unroll
                for (int n = 0; n < 4; ++n) {
                    uint32_t w0 = wq[2 * n], w1r = wq[2 * n + 1];
                    #pragma unroll
                    for (int r = 0; r < 4; ++r)
                        mma_f16(c2[r][n], af[r][0], af[r][1], af[r][2], af[r][3], w0, w1r);
                }
            }

            // ---- layer-3 dot as MMA, 4 rows interleaved (no shuffles) ----
            float cd[4][4];
            #pragma unroll
            for (int r = 0; r < 4; ++r) {
                cd[r][0] = bias3; cd[r][1] = bias3;
                cd[r][2] = bias3; cd[r][3] = bias3;
            }
            #pragma unroll
            for (int ks = 0; ks < 2; ++ks) {
                #pragma unroll
                for (int r = 0; r < 4; ++r) {
                    uint32_t a0 = packh2(leaky(c2[r][2 * ks][0]),     leaky(c2[r][2 * ks][1]));
                    uint32_t a1 = packh2(leaky(c2[r][2 * ks][2]),     leaky(c2[r][2 * ks][3]));
                    uint32_t a2 = packh2(leaky(c2[r][2 * ks + 1][0]), leaky(c2[r][2 * ks + 1][1]));
                    uint32_t a3 = packh2(leaky(c2[r][2 * ks + 1][2]), leaky(c2[r][2 * ks + 1][3]));
                    mma_f16(cd[r], a0, a1, a2, a3, w3f[2 * ks], w3f[2 * ks + 1]);
                }
            }

            if (t == 0) {
                const int jg = tj * 64 + jm * 16 + g;
                #pragma unroll
                for (int r = 0; r < 4; ++r) {
                    const int ig = ig0 + r;
                    ob[(size_t)ig * NN + jg]     = cd[r][0];
                    ob[(size_t)ig * NN + jg + 8] = cd[r][2];
                    if (ti != tj) {   // mirror (logits exactly symmetric)
                        ob[(size_t)jg * NN + ig]       = cd[r][0];
                        ob[(size_t)(jg + 8) * NN + ig] = cd[r][2];
                    }
                }
            }
        }
    }
}

// ---------------------------------------------------------------------------
// Row softmax, warp-per-row: 16 rows per 512-thread block, 128 blocks.
// ---------------------------------------------------------------------------
__global__ __launch_bounds__(512)
void adj_softmax_kernel(float* __restrict__ out)
{
    const int row  = blockIdx.x * 16 + (threadIdx.x >> 5);
    const int lane = threadIdx.x & 31;
    float4* __restrict__ p = (float4*)(out + (size_t)row * NN);

    float4 x0 = p[lane];
    float4 x1 = p[lane + 32];
    float4 x2 = p[lane + 64];
    float4 x3 = p[lane + 96];

    float m = fmaxf(fmaxf(fmaxf(x0.x, x0.y), fmaxf(x0.z, x0.w)),
                    fmaxf(fmaxf(x1.x, x1.y), fmaxf(x1.z, x1.w)));
    m = fmaxf(m, fmaxf(fmaxf(fmaxf(x2.x, x2.y), fmaxf(x2.z, x2.w)),
                       fmaxf(fmaxf(x3.x, x3.y), fmaxf(x3.z, x3.w))));
    #pragma unroll
    for (int o = 16; o; o >>= 1) m = fmaxf(m, __shfl_xor_sync(0xFFFFFFFFu, m, o));

    x0.x = __expf(x0.x - m); x0.y = __expf(x0.y - m);
    x0.z = __expf(x0.z - m); x0.w = __expf(x0.w - m);
    x1.x = __expf(x1.x - m); x1.y = __expf(x1.y - m);
    x1.z = __expf(x1.z - m); x1.w = __expf(x1.w - m);
    x2.x = __expf(x2.x - m); x2.y = __expf(x2.y - m);
    x2.z = __expf(x2.z - m); x2.w = __expf(x2.w - m);
    x3.x = __expf(x3.x - m); x3.y = __expf(x3.y - m);
    x3.z = __expf(x3.z - m); x3.w = __expf(x3.w - m);

    float s = ((x0.x + x0.y) + (x0.z + x0.w)) + ((x1.x + x1.y) + (x1.z + x1.w))
            + ((x2.x + x2.y) + (x2.z + x2.w)) + ((x3.x + x3.y) + (x3.z + x3.w));
    #pragma unroll
    for (int o = 16; o; o >>= 1) s += __shfl_xor_sync(0xFFFFFFFFu, s, o);

    float inv = __fdividef(1.0f, s);
    x0.x *= inv; x0.y *= inv; x0.z *= inv; x0.w *= inv;
    x1.x *= inv; x1.y *= inv; x1.z *= inv; x1.w *= inv;
    x2.x *= inv; x2.y *= inv; x2.z *= inv; x2.w *= inv;
    x3.x *= inv; x3.y *= inv; x3.z *= inv; x3.w *= inv;

    p[lane]      = x0;
    p[lane + 32] = x1;
    p[lane + 64] = x2;
    p[lane + 96] = x3;
}

extern "C" void kernel_launch(void* const* d_in, const int* in_sizes, int n_in,
                              void* d_out, int out_size)
{
    const float* v  = (const float*)d_in[0];
    const float* W1 = (const float*)d_in[1];
    const float* b1 = (const float*)d_in[2];
    const float* W2 = (const float*)d_in[3];
    const float* b2 = (const float*)d_in[4];
    const float* W3 = (const float*)d_in[5];
    const float* b3 = (const float*)d_in[6];
    float* out = (float*)d_out;

    cudaFuncSetAttribute(adj_hmma_kernel,
                         cudaFuncAttributeMaxDynamicSharedMemorySize, SMEM_TOTAL);

    dim3 grid(NPAIRS, NB);   // (36, 4) — one wave of 144 CTAs
    adj_hmma_kernel<<<grid, THREADS, SMEM_TOTAL>>>(v, W1, b1, W2, b2, W3, b3, out);
    adj_softmax_kernel<<<NB * NN / 16, 512>>>(out);
}

// round 17
// speedup vs baseline: 1.3757x; 1.0941x over previous
#include <cuda_runtime.h>
#include <stdint.h>

#define NB 4
#define NN 512
#define DD 128
#define H1C 64
#define H2C 32
#define NT 8                       // 512/64 tiles
#define NPAIRS (NT * (NT + 1) / 2) // 36
#define THREADS 256

// ---- dynamic shared memory layout (bytes) ----
#define OFF_VIH  0                 // 64*68*4 = 17408
#define OFF_VJH  17408             // 17408
#define OFF_W1H  34816             // 64 rows x 68 u32 (half2 table) = 17408
#define OFF_W2F  52224             // 4 ks x 32 lane x 8 u32 = 4096
#define OFF_B1S  56320             // 64 f
#define OFF_B2S  56576             // 32 f
#define SMEM_TOTAL 56704

static __device__ __forceinline__ uint32_t packh2(float lo, float hi) {
    uint32_t u;
    asm("cvt.rn.f16x2.f32 %0, %1, %2;" : "=r"(u) : "f"(hi), "f"(lo));
    return u;
}
static __device__ __forceinline__ uint32_t habs2_sub(uint32_t a, uint32_t b) {
    uint32_t d;
    asm("sub.f16x2 %0, %1, %2;" : "=r"(d) : "r"(a), "r"(b));
    return d & 0x7FFF7FFFu;
}
// packed leaky on f16x2: max(x, 0.1*x)   (0.1 in fp16 = 0x2E66)
static __device__ __forceinline__ uint32_t leaky_h2(uint32_t x) {
    uint32_t s, r;
    asm("mul.f16x2 %0, %1, %2;" : "=r"(s) : "r"(x), "r"(0x2E662E66u));
    asm("max.f16x2 %0, %1, %2;" : "=r"(r) : "r"(x), "r"(s));
    return r;
}
// fp32-accumulator MMA
static __device__ __forceinline__ void mma_f16(float* c,
        uint32_t a0, uint32_t a1, uint32_t a2, uint32_t a3,
        uint32_t b0, uint32_t b1) {
    asm volatile(
        "mma.sync.aligned.m16n8k16.row.col.f32.f16.f16.f32 "
        "{%0,%1,%2,%3}, {%4,%5,%6,%7}, {%8,%9}, {%0,%1,%2,%3};"
        : "+f"(c[0]), "+f"(c[1]), "+f"(c[2]), "+f"(c[3])
        : "r"(a0), "r"(a1), "r"(a2), "r"(a3), "r"(b0), "r"(b1));
}
// fp16-accumulator MMA (D/C are f16x2 pairs: d0 = rows g, d1 = rows g+8)
static __device__ __forceinline__ void mma_f16acc(uint32_t& d0, uint32_t& d1,
        uint32_t a0, uint32_t a1, uint32_t a2, uint32_t a3,
        uint32_t b0, uint32_t b1) {
    asm volatile(
        "mma.sync.aligned.m16n8k16.row.col.f16.f16.f16.f16 "
        "{%0,%1}, {%2,%3,%4,%5}, {%6,%7}, {%0,%1};"
        : "+r"(d0), "+r"(d1)
        : "r"(a0), "r"(a1), "r"(a2), "r"(a3), "r"(b0), "r"(b1));
}
static __device__ __forceinline__ float leaky(float x) { return fmaxf(x, 0.1f * x); }

// ---------------------------------------------------------------------------
// Symmetric fp16-HMMA logits kernel.
//  - W1 fragments register-resident; 2-i-row GEMM1 blocking.
//  - GEMM1 uses fp16 ACCUMULATORS (half the registers; 2x rate if the
//    compat path follows the consumer rule).  GEMM2 + dot stay fp32-acc.
//  - leaky applied as packed f16x2 ops directly on accumulator registers.
//  - layer-3 dot as MMA with w3 replicated across B columns (no shuffles).
// CTA = (batch, tile-pair ti<=tj, 64x64); 8 warps, 1 CTA/SM, one wave.
// ---------------------------------------------------------------------------
__global__ __launch_bounds__(THREADS, 1)
void adj_hmma_kernel(const float* __restrict__ v,
                     const float* __restrict__ W1, const float* __restrict__ b1,
                     const float* __restrict__ W2, const float* __restrict__ b2,
                     const float* __restrict__ W3, const float* __restrict__ b3,
                     float* __restrict__ out)
{
    extern __shared__ char sm[];
    uint32_t* VIH = (uint32_t*)(sm + OFF_VIH);
    uint32_t* VJH = (uint32_t*)(sm + OFF_VJH);
    uint32_t* W1H = (uint32_t*)(sm + OFF_W1H);
    uint32_t* W2F = (uint32_t*)(sm + OFF_W2F);
    float*    B1S = (float*)(sm + OFF_B1S);
    float*    B2S = (float*)(sm + OFF_B2S);

    const int tid  = threadIdx.x;
    const int wid  = tid >> 5;
    const int lane = tid & 31;
    const int g    = lane >> 2;   // groupID (row within fragment)
    const int t    = lane & 3;    // threadID_in_group
    const int b    = blockIdx.y;

    // decode (ti, tj), ti <= tj
    int rem = blockIdx.x;
    int ti = 0;
    while (rem >= NT - ti) { rem -= NT - ti; ti++; }
    const int tj = ti + rem;

    // ---- stage v tiles -> half2 SMEM (rows padded to 68 u32) ----
    const float* vb = v + (size_t)b * NN * DD;
    for (int e = tid; e < 64 * 32; e += THREADS) {
        int r = e >> 5, c = e & 31;
        float4 xi = ((const float4*)(vb + (size_t)(ti * 64 + r) * DD))[c];
        float4 xj = ((const float4*)(vb + (size_t)(tj * 64 + r) * DD))[c];
        VIH[r * 68 + 2 * c]     = packh2(xi.x, xi.y);
        VIH[r * 68 + 2 * c + 1] = packh2(xi.z, xi.w);
        VJH[r * 68 + 2 * c]     = packh2(xj.x, xj.y);
        VJH[r * 68 + 2 * c + 1] = packh2(xj.z, xj.w);
    }
    // ---- stage W1 as half2 table: W1H[o][k/2], rows padded to 68 ----
    for (int e = tid; e < 64 * 64; e += THREADS) {
        int o = e >> 6, ci = e & 63;
        W1H[o * 68 + ci] = packh2(W1[o * DD + 2 * ci], W1[o * DD + 2 * ci + 1]);
    }
    // ---- W2 half2 fragments: [ks(4)][lane(32)][n(4)x{b0,b1}] ----
    for (int idx = tid; idx < 4 * 32 * 8; idx += THREADS) {
        int ks = idx >> 8, ln = (idx >> 3) & 31, rm = idx & 7;
        int n = rm >> 1, e = rm & 1;
        int o  = (ln >> 2) + 8 * n;
        int kb = 16 * ks + 2 * (ln & 3) + 8 * e;
        W2F[idx] = packh2(W2[o * H1C + kb], W2[o * H1C + kb + 1]);
    }
    if (tid < H1C) B1S[tid] = b1[tid];
    if (tid < H2C) B2S[tid] = b2[tid];
    const float bias3 = b3[0];

    // w3 B-fragments, replicated across columns (independent of g): 4 regs
    uint32_t w3f[4];
    #pragma unroll
    for (int ks = 0; ks < 2; ++ks)
        #pragma unroll
        for (int e = 0; e < 2; ++e) {
            int k = 16 * ks + 2 * t + 8 * e;
            w3f[2 * ks + e] = packh2(W3[k], W3[k + 1]);
        }
    __syncthreads();

    // ---- gather W1 fragments into registers (one-time, conflict-free) ----
    uint32_t w1f[8][16];
    #pragma unroll
    for (int ks = 0; ks < 8; ++ks)
        #pragma unroll
        for (int n = 0; n < 8; ++n) {
            w1f[ks][2 * n]     = W1H[(g + 8 * n) * 68 + 8 * ks + t];
            w1f[ks][2 * n + 1] = W1H[(g + 8 * n) * 68 + 8 * ks + t + 4];
        }

    float* ob = out + (size_t)b * NN * NN;

    for (int jm = 0; jm < 4; ++jm) {
        // hoist this jm's vj fragments (reused by all 4 row-pairs)
        uint32_t vj[8][4];
        #pragma unroll
        for (int ks = 0; ks < 8; ++ks) {
            vj[ks][0] = VJH[(jm * 16 + g) * 68 + 8 * ks + t];
            vj[ks][1] = VJH[(jm * 16 + 8 + g) * 68 + 8 * ks + t];
            vj[ks][2] = VJH[(jm * 16 + g) * 68 + 8 * ks + t + 4];
            vj[ks][3] = VJH[(jm * 16 + 8 + g) * 68 + 8 * ks + t + 4];
        }

        for (int rp = 0; rp < 4; ++rp) {
            const int il0 = wid * 8 + rp * 2;
            const int ig0 = ti * 64 + il0;

            // ---- GEMM1 (2 rows), fp16 accumulators: h1 = |vi-vj| @ W1^T ----
            // c1h[r][n][0] = rows g pair (ch 8n+2t, +1); [1] = rows g+8 pair
            uint32_t c1h[2][8][2];
            #pragma unroll
            for (int n = 0; n < 8; ++n) {
                uint32_t bb = packh2(B1S[8 * n + 2 * t], B1S[8 * n + 2 * t + 1]);
                #pragma unroll
                for (int r = 0; r < 2; ++r) {
                    c1h[r][n][0] = bb;
                    c1h[r][n][1] = bb;
                }
            }
            #pragma unroll
            for (int ks = 0; ks < 8; ++ks) {
                uint32_t vl0 = VIH[il0 * 68 + 8 * ks + t];
                uint32_t vh0 = VIH[il0 * 68 + 8 * ks + t + 4];
                uint32_t vl1 = VIH[(il0 + 1) * 68 + 8 * ks + t];
                uint32_t vh1 = VIH[(il0 + 1) * 68 + 8 * ks + t + 4];
                uint32_t a00 = habs2_sub(vl0, vj[ks][0]);
                uint32_t a10 = habs2_sub(vl0, vj[ks][1]);
                uint32_t a20 = habs2_sub(vh0, vj[ks][2]);
                uint32_t a30 = habs2_sub(vh0, vj[ks][3]);
                uint32_t a01 = habs2_sub(vl1, vj[ks][0]);
                uint32_t a11 = habs2_sub(vl1, vj[ks][1]);
                uint32_t a21 = habs2_sub(vh1, vj[ks][2]);
                uint32_t a31 = habs2_sub(vh1, vj[ks][3]);
                #pragma unroll
                for (int n = 0; n < 8; ++n) {
                    uint32_t w0 = w1f[ks][2 * n], w1r = w1f[ks][2 * n + 1];
                    mma_f16acc(c1h[0][n][0], c1h[0][n][1], a00, a10, a20, a30, w0, w1r);
                    mma_f16acc(c1h[1][n][0], c1h[1][n][1], a01, a11, a21, a31, w0, w1r);
                }
            }

            // ---- per row: GEMM2 (fp32 acc) then dot-MMA (no shuffles) ----
            #pragma unroll
            for (int r = 0; r < 2; ++r) {
                float c2[4][4];
                #pragma unroll
                for (int n = 0; n < 4; ++n) {
                    c2[n][0] = B2S[8 * n + 2 * t];
                    c2[n][1] = B2S[8 * n + 2 * t + 1];
                    c2[n][2] = c2[n][0];
                    c2[n][3] = c2[n][1];
                }
                #pragma unroll
                for (int ks = 0; ks < 4; ++ks) {
                    // A-frags: packed leaky directly on fp16 accumulators
                    uint32_t a0 = leaky_h2(c1h[r][2 * ks][0]);
                    uint32_t a1 = leaky_h2(c1h[r][2 * ks][1]);
                    uint32_t a2 = leaky_h2(c1h[r][2 * ks + 1][0]);
                    uint32_t a3 = leaky_h2(c1h[r][2 * ks + 1][1]);
                    const uint32_t* wq = W2F + ks * 256 + lane * 8;
                    #pragma unroll
                    for (int n = 0; n < 4; ++n)
                        mma_f16(c2[n], a0, a1, a2, a3, wq[2 * n], wq[2 * n + 1]);
                }

                // layer-3 dot as MMA: c[0]=row g, c[2]=row g+8 on all threads
                float cd[4] = {bias3, bias3, bias3, bias3};
                #pragma unroll
                for (int ks = 0; ks < 2; ++ks) {
                    uint32_t a0 = packh2(leaky(c2[2 * ks][0]),     leaky(c2[2 * ks][1]));
                    uint32_t a1 = packh2(leaky(c2[2 * ks][2]),     leaky(c2[2 * ks][3]));
                    uint32_t a2 = packh2(leaky(c2[2 * ks + 1][0]), leaky(c2[2 * ks + 1][1]));
                    uint32_t a3 = packh2(leaky(c2[2 * ks + 1][2]), leaky(c2[2 * ks + 1][3]));
                    mma_f16(cd, a0, a1, a2, a3, w3f[2 * ks], w3f[2 * ks + 1]);
                }

                if (t == 0) {
                    const int ig = ig0 + r;
                    const int jg = tj * 64 + jm * 16 + g;
                    ob[(size_t)ig * NN + jg]     = cd[0];
                    ob[(size_t)ig * NN + jg + 8] = cd[2];
                    if (ti != tj) {   // mirror (logits exactly symmetric)
                        ob[(size_t)jg * NN + ig]       = cd[0];
                        ob[(size_t)(jg + 8) * NN + ig] = cd[2];
                    }
                }
            }
        }
    }
}

// ---------------------------------------------------------------------------
// Row softmax, warp-per-row: 16 rows per 512-thread block, 128 blocks.
// ---------------------------------------------------------------------------
__global__ __launch_bounds__(512)
void adj_softmax_kernel(float* __restrict__ out)
{
    const int row  = blockIdx.x * 16 + (threadIdx.x >> 5);
    const int lane = threadIdx.x & 31;
    float4* __restrict__ p = (float4*)(out + (size_t)row * NN);

    float4 x0 = p[lane];
    float4 x1 = p[lane + 32];
    float4 x2 = p[lane + 64];
    float4 x3 = p[lane + 96];

    float m = fmaxf(fmaxf(fmaxf(x0.x, x0.y), fmaxf(x0.z, x0.w)),
                    fmaxf(fmaxf(x1.x, x1.y), fmaxf(x1.z, x1.w)));
    m = fmaxf(m, fmaxf(fmaxf(fmaxf(x2.x, x2.y), fmaxf(x2.z, x2.w)),
                       fmaxf(fmaxf(x3.x, x3.y), fmaxf(x3.z, x3.w))));
    #pragma unroll
    for (int o = 16; o; o >>= 1) m = fmaxf(m, __shfl_xor_sync(0xFFFFFFFFu, m, o));

    x0.x = __expf(x0.x - m); x0.y = __expf(x0.y - m);
    x0.z = __expf(x0.z - m); x0.w = __expf(x0.w - m);
    x1.x = __expf(x1.x - m); x1.y = __expf(x1.y - m);
    x1.z = __expf(x1.z - m); x1.w = __expf(x1.w - m);
    x2.x = __expf(x2.x - m); x2.y = __expf(x2.y - m);
    x2.z = __expf(x2.z - m); x2.w = __expf(x2.w - m);
    x3.x = __expf(x3.x - m); x3.y = __expf(x3.y - m);
    x3.z = __expf(x3.z - m); x3.w = __expf(x3.w - m);

    float s = ((x0.x + x0.y) + (x0.z + x0.w)) + ((x1.x + x1.y) + (x1.z + x1.w))
            + ((x2.x + x2.y) + (x2.z + x2.w)) + ((x3.x + x3.y) + (x3.z + x3.w));
    #pragma unroll
    for (int o = 16; o; o >>= 1) s += __shfl_xor_sync(0xFFFFFFFFu, s, o);

    float inv = __fdividef(1.0f, s);
    x0.x *= inv; x0.y *= inv; x0.z *= inv; x0.w *= inv;
    x1.x *= inv; x1.y *= inv; x1.z *= inv; x1.w *= inv;
    x2.x *= inv; x2.y *= inv; x2.z *= inv; x2.w *= inv;
    x3.x *= inv; x3.y *= inv; x3.z *= inv; x3.w *= inv;

    p[lane]      = x0;
    p[lane + 32] = x1;
    p[lane + 64] = x2;
    p[lane + 96] = x3;
}

extern "C" void kernel_launch(void* const* d_in, const int* in_sizes, int n_in,
                              void* d_out, int out_size)
{
    const float* v  = (const float*)d_in[0];
    const float* W1 = (const float*)d_in[1];
    const float* b1 = (const float*)d_in[2];
    const float* W2 = (const float*)d_in[3];
    const float* b2 = (const float*)d_in[4];
    const float* W3 = (const float*)d_in[5];
    const float* b3 = (const float*)d_in[6];
    float* out = (float*)d_out;

    cudaFuncSetAttribute(adj_hmma_kernel,
                         cudaFuncAttributeMaxDynamicSharedMemorySize, SMEM_TOTAL);

    dim3 grid(NPAIRS, NB);   // (36, 4) — one wave of 144 CTAs
    adj_hmma_kernel<<<grid, THREADS, SMEM_TOTAL>>>(v, W1, b1, W2, b2, W3, b3, out);
    adj_softmax_kernel<<<NB * NN / 16, 512>>>(out);
}